// round 10
// baseline (speedup 1.0000x reference)
#include <cuda_runtime.h>
#include <cuda_bf16.h>
#include <math.h>
#include <stdint.h>

// Problem constants
#define Bb   64
#define NPG  400
#define Kk   250
#define Ff   64
#define LIN  16000
#define Hh   8000
#define Nn   (Bb*NPG)        // 25600
#define BN_EPS 1e-5f

#define KSPLIT 7
#define KCH    2304          // 6 chunks of 2304 + 1 of 2176 = 16000 (both /32)
#define G2SPLIT 16

// Scratch (device globals; no allocation allowed)
__device__ __nv_bfloat16 g_xb[Bb*LIN];      // bf16 normalized features
__device__ float g_hpart[KSPLIT][Bb][Hh];   // split-K partials
__device__ float g_l2[Bb*G2SPLIT];          // gemm2 partial logits

// ---------------------------------------------------------------------------
// Kernel: fused scores + bitonic top-K + gather + tanh + BatchNorm -> bf16 xn
// One block per graph, 512 threads.
// ---------------------------------------------------------------------------
__global__ void k_pool(const float* __restrict__ feat, const float* __restrict__ w,
                       const float* __restrict__ bn_mean, const float* __restrict__ bn_var,
                       const float* __restrict__ bn_gamma, const float* __restrict__ bn_beta) {
    __shared__ float sv[512];
    __shared__ int   si[512];
    __shared__ float s_inv;
    int tid = threadIdx.x, b = blockIdx.x;
    int warp = tid >> 5, lane = tid & 31;

    if (tid == 0) {
        float s = 0.f;
        #pragma unroll
        for (int i = 0; i < Ff; i++) s += w[i] * w[i];
        s_inv = rsqrtf(s);
    }
    const float* xg = feat + (size_t)11 * Nn * Ff + (size_t)b * NPG * Ff;
    float wl0 = w[lane], wl1 = w[lane + 32];
    for (int nd = warp; nd < NPG; nd += 16) {
        const float* x = xg + (size_t)nd * Ff;
        float v = x[lane] * wl0 + x[lane + 32] * wl1;
        #pragma unroll
        for (int o = 16; o > 0; o >>= 1) v += __shfl_down_sync(0xffffffffu, v, o);
        if (lane == 0) sv[nd] = v;
    }
    if (tid >= NPG) sv[tid] = __int_as_float(0xff800000);
    si[tid] = tid;
    __syncthreads();

    // Bitonic sort: value descending, index ascending on ties
    for (int k = 2; k <= 512; k <<= 1) {
        for (int j = k >> 1; j > 0; j >>= 1) {
            int ixj = tid ^ j;
            if (ixj > tid) {
                float va = sv[tid], vb = sv[ixj];
                int   ia = si[tid], ib = si[ixj];
                bool aFirst = (va > vb) || (va == vb && ia < ib);
                bool bFirst = (vb > va) || (vb == va && ib < ia);
                bool desc = ((tid & k) == 0);
                bool sw = desc ? bFirst : aFirst;
                if (sw) { sv[tid] = vb; sv[ixj] = va; si[tid] = ib; si[ixj] = ia; }
            }
            __syncthreads();
        }
    }

    // replace sorted score by tanh(score/||w||) in-place
    if (tid < Kk) sv[tid] = tanhf(sv[tid] * s_inv);
    __syncthreads();

    // gather + BN + bf16 store
    for (int i = tid; i < LIN; i += 512) {
        int r = i >> 6, f = i & 63;
        float xv = xg[si[r] * Ff + f];
        float xn = (xv * sv[r] - bn_mean[i]) * rsqrtf(bn_var[i] + BN_EPS) * bn_gamma[i] + bn_beta[i];
        g_xb[(size_t)b * LIN + i] = __float2bfloat16(xn);
    }
}

// ---------------------------------------------------------------------------
// GEMM1:  hpart[s][m][j] = sum_{k in chunk s} xn[m,k] * W1[j,k]
// bf16 mma.sync m16n8k16, W fp32->bf16 in-register, ldmatrix fragments.
// Block 256 thr (8 warps), warp tile 32m x 32j, BK=32, 2-stage smem,
// ONE barrier per iter, LDG prefetch issued before the barrier.
// 3 CTAs/SM. grid (63, 7) = 441 CTAs = one wave.
// ---------------------------------------------------------------------------
#define BN1   128
#define BK1   32
#define ROWB  80                    // bytes per smem row (40 halves)
#define W_BYTES (128 * ROWB)        // 10240
#define X_BYTES (64 * ROWB)         // 5120
#define STG_B   (W_BYTES + X_BYTES) // 15360

__device__ __forceinline__ void mma16816(float* d,
                                         unsigned a0, unsigned a1, unsigned a2, unsigned a3,
                                         unsigned b0, unsigned b1) {
    asm volatile(
        "mma.sync.aligned.m16n8k16.row.col.f32.bf16.bf16.f32 "
        "{%0,%1,%2,%3}, {%4,%5,%6,%7}, {%8,%9}, {%0,%1,%2,%3};\n"
        : "+f"(d[0]), "+f"(d[1]), "+f"(d[2]), "+f"(d[3])
        : "r"(a0), "r"(a1), "r"(a2), "r"(a3), "r"(b0), "r"(b1));
}

__device__ __forceinline__ void ldsm4(unsigned& r0, unsigned& r1, unsigned& r2, unsigned& r3,
                                      unsigned addr) {
    asm volatile("ldmatrix.sync.aligned.m8n8.x4.shared.b16 {%0,%1,%2,%3}, [%4];"
                 : "=r"(r0), "=r"(r1), "=r"(r2), "=r"(r3) : "r"(addr));
}

__global__ __launch_bounds__(256, 3) void k_gemm1(const float* __restrict__ W1) {
    __shared__ __align__(16) unsigned char sm[2 * STG_B];
    unsigned smbase = (unsigned)__cvta_generic_to_shared(sm);

    int tid  = threadIdx.x;
    int warp = tid >> 5, lane = tid & 31;
    int wm = warp >> 2, wj = warp & 3;
    int gi = lane >> 2, qi = lane & 3;
    int jbase = blockIdx.x * BN1;
    int kbase = blockIdx.y * KCH;
    int iters = (blockIdx.y == KSPLIT - 1) ? 68 : 72;   // 68*32=2176, 72*32=2304

    // W load mapping: 4 float4/thread. chunk c = tid + i*256: row=c>>3, c8=c&7
    const float* wsrc[4]; unsigned wdst[4];
    #pragma unroll
    for (int i = 0; i < 4; i++) {
        int c = tid + i * 256;
        int row = c >> 3, c8 = c & 7;
        int j = jbase + row; if (j > Hh - 1) j = Hh - 1;
        wsrc[i] = W1 + (size_t)j * LIN + kbase + c8 * 4;
        wdst[i] = smbase + row * ROWB + c8 * 8;
    }
    // X load mapping: all 256 threads, 1 uint4 (8 halves). row=tid>>2, seg=tid&3
    const __nv_bfloat16* xsrc; unsigned xdst;
    {
        int row = tid >> 2, seg = tid & 3;
        xsrc = g_xb + (size_t)row * LIN + kbase + seg * 8;
        xdst = smbase + W_BYTES + row * ROWB + seg * 16;
    }

    // ldmatrix per-lane offsets (row stride 80B; conflict-free)
    unsigned offA = (unsigned)((lane & 15) * ROWB + (lane >> 4) * 16);
    unsigned offB = (unsigned)((((lane >> 4) & 1) * 8 + (lane & 7)) * ROWB + ((lane >> 3) & 1) * 16);
    unsigned aAddr0 = smbase + W_BYTES + (wm * 32) * ROWB + offA;       // mt=0
    unsigned aAddr1 = aAddr0 + 16 * ROWB;                                // mt=1
    unsigned bAddr0 = smbase + (wj * 32) * ROWB + offB;                  // nt pair 0
    unsigned bAddr1 = bAddr0 + 16 * ROWB;                                // nt pair 1

    float acc[2][4][4];
    #pragma unroll
    for (int a = 0; a < 2; a++)
        #pragma unroll
        for (int b = 0; b < 4; b++)
            #pragma unroll
            for (int q = 0; q < 4; q++) acc[a][b][q] = 0.f;

    // prologue: iter-0 data into registers
    float4 wv[4];
    #pragma unroll
    for (int i = 0; i < 4; i++) wv[i] = *(const float4*)(wsrc[i]);
    uint4 x0 = *(const uint4*)(xsrc);

    for (int it = 0; it < iters; it++) {
        unsigned st = (unsigned)(it & 1) * STG_B;

        // STS: convert W to bf16 (8B each), copy X (16B)
        #pragma unroll
        for (int i = 0; i < 4; i++) {
            __nv_bfloat162 p0 = __floats2bfloat162_rn(wv[i].x, wv[i].y);
            __nv_bfloat162 p1 = __floats2bfloat162_rn(wv[i].z, wv[i].w);
            asm volatile("st.shared.v2.b32 [%0], {%1,%2};"
                         :: "r"(wdst[i] + st), "r"(*(unsigned*)&p0), "r"(*(unsigned*)&p1));
        }
        asm volatile("st.shared.v4.b32 [%0], {%1,%2,%3,%4};"
                     :: "r"(xdst + st), "r"(x0.x), "r"(x0.y), "r"(x0.z), "r"(x0.w));

        // prefetch next iteration BEFORE the barrier: LDG covers barrier wait
        // + MMA phase before its consumer (next iter's STS).
        if (it + 1 < iters) {
            int ko = (it + 1) * BK1;
            #pragma unroll
            for (int i = 0; i < 4; i++) wv[i] = *(const float4*)(wsrc[i] + ko);
            x0 = *(const uint4*)(xsrc + ko);
        }

        // Single barrier per iteration. Safe: reads of stage s at iter it-1
        // precede STS(it) in program order, so this barrier also orders them
        // against the overwrite of stage s at iter it+1.
        __syncthreads();

        // two k16 sub-chunks
        #pragma unroll
        for (int kk = 0; kk < 2; kk++) {
            unsigned ko = (unsigned)(kk * 32);   // 16 halves = 32B
            unsigned a0[2], a1[2], a2[2], a3[2];
            ldsm4(a0[0], a1[0], a2[0], a3[0], aAddr0 + st + ko);
            ldsm4(a0[1], a1[1], a2[1], a3[1], aAddr1 + st + ko);
            unsigned b00, b01, b10, b11;
            ldsm4(b00, b01, b10, b11, bAddr0 + st + ko);
            #pragma unroll
            for (int mt = 0; mt < 2; mt++) {
                mma16816(acc[mt][0], a0[mt], a1[mt], a2[mt], a3[mt], b00, b01);
                mma16816(acc[mt][1], a0[mt], a1[mt], a2[mt], a3[mt], b10, b11);
            }
            ldsm4(b00, b01, b10, b11, bAddr1 + st + ko);
            #pragma unroll
            for (int mt = 0; mt < 2; mt++) {
                mma16816(acc[mt][2], a0[mt], a1[mt], a2[mt], a3[mt], b00, b01);
                mma16816(acc[mt][3], a0[mt], a1[mt], a2[mt], a3[mt], b10, b11);
            }
        }
    }

    // epilogue: plain STG into split-private partials
    float* hp = &g_hpart[blockIdx.y][0][0];
    #pragma unroll
    for (int mt = 0; mt < 2; mt++) {
        #pragma unroll
        for (int nt = 0; nt < 4; nt++) {
            int m = wm * 32 + mt * 16 + gi;
            int j = jbase + wj * 32 + nt * 8 + qi * 2;
            if (j < Hh) {
                *(float2*)(hp + (size_t)m * Hh + j) =
                    make_float2(acc[mt][nt][0], acc[mt][nt][1]);
                *(float2*)(hp + (size_t)(m + 8) * Hh + j) =
                    make_float2(acc[mt][nt][2], acc[mt][nt][3]);
            }
        }
    }
}

// ---------------------------------------------------------------------------
// GEMM2 + split-reduce + bias + relu.  grid (64, 16), 128 thr.
// ---------------------------------------------------------------------------
__global__ void k_gemm2(const float* __restrict__ b1, const float* __restrict__ W2) {
    int m = blockIdx.x, q = blockIdx.y, tid = threadIdx.x;
    int jq = q * (Hh / G2SPLIT);          // 500 per split
    float s = 0.f;
    for (int t = tid * 4; t < Hh / G2SPLIT; t += 512) {
        int j = jq + t;
        float4 hs = make_float4(0.f, 0.f, 0.f, 0.f);
        #pragma unroll
        for (int sp = 0; sp < KSPLIT; sp++) {
            float4 hv = *(const float4*)(&g_hpart[sp][m][j]);
            hs.x += hv.x; hs.y += hv.y; hs.z += hv.z; hs.w += hv.w;
        }
        float4 bv = *(const float4*)(b1 + j);
        float4 wv = *(const float4*)(W2 + j);
        s += fmaxf(hs.x + bv.x, 0.f) * wv.x;
        s += fmaxf(hs.y + bv.y, 0.f) * wv.y;
        s += fmaxf(hs.z + bv.z, 0.f) * wv.z;
        s += fmaxf(hs.w + bv.w, 0.f) * wv.w;
    }
    #pragma unroll
    for (int o = 16; o > 0; o >>= 1) s += __shfl_down_sync(0xffffffffu, s, o);
    __shared__ float red[4];
    if ((tid & 31) == 0) red[tid >> 5] = s;
    __syncthreads();
    if (tid == 0)
        g_l2[m * G2SPLIT + q] = red[0] + red[1] + red[2] + red[3];
}

// ---------------------------------------------------------------------------
// Loss
// ---------------------------------------------------------------------------
__global__ void k_loss(const float* __restrict__ b2, float* __restrict__ out) {
    int tid = threadIdx.x;  // 64 threads
    float l = b2[0];
    #pragma unroll
    for (int q = 0; q < G2SPLIT; q++) l += g_l2[tid * G2SPLIT + q];
    float per = (l > 0.f) ? log1pf(expf(-l)) : (log1pf(expf(l)) - l);
    #pragma unroll
    for (int o = 16; o > 0; o >>= 1) per += __shfl_down_sync(0xffffffffu, per, o);
    __shared__ float r2[2];
    if ((tid & 31) == 0) r2[tid >> 5] = per;
    __syncthreads();
    if (tid == 0) out[0] = (r2[0] + r2[1]) * (1.0f / Bb);
}

// ---------------------------------------------------------------------------
extern "C" void kernel_launch(void* const* d_in, const int* in_sizes, int n_in,
                              void* d_out, int out_size) {
    const float* feat     = (const float*)d_in[0];
    const float* w        = (const float*)d_in[3];
    const float* bn_gamma = (const float*)d_in[4];
    const float* bn_beta  = (const float*)d_in[5];
    const float* bn_mean  = (const float*)d_in[6];
    const float* bn_var   = (const float*)d_in[7];
    const float* W1       = (const float*)d_in[8];
    const float* b1       = (const float*)d_in[9];
    const float* W2       = (const float*)d_in[10];
    const float* b2       = (const float*)d_in[11];

    k_pool<<<Bb, 512>>>(feat, w, bn_mean, bn_var, bn_gamma, bn_beta);
    dim3 g1(63, KSPLIT);   // 441 CTAs, 3/SM -> one wave
    k_gemm1<<<g1, 256>>>(W1);
    dim3 g2(Bb, G2SPLIT);
    k_gemm2<<<g2, 128>>>(b1, W2);
    k_loss<<<1, 64>>>(b2, (float*)d_out);
}

// round 11
// speedup vs baseline: 1.0396x; 1.0396x over previous
#include <cuda_runtime.h>
#include <cuda_bf16.h>
#include <math.h>
#include <stdint.h>

// Problem constants
#define Bb   64
#define NPG  400
#define Kk   250
#define Ff   64
#define LIN  16000
#define Hh   8000
#define Nn   (Bb*NPG)        // 25600
#define BN_EPS 1e-5f

#define KSPLIT 7
#define KCH    2304          // 6 chunks of 2304 + 1 of 2176 = 16000 (both /32)
#define G2SPLIT 16

// Scratch (device globals; no allocation allowed)
__device__ __nv_bfloat16 g_xb[Bb*LIN];      // bf16 normalized features
__device__ int   g_selidx[Bb*Kk];
__device__ float g_stanh[Bb*Kk];
__device__ float g_hpart[KSPLIT][Bb][Hh];   // split-K partials
__device__ float g_l2[Bb*G2SPLIT];          // gemm2 partial logits
__device__ int   g_done;                    // gemm2 completion counter (zero-init)

// ---------------------------------------------------------------------------
// Kernel: fused scores + bitonic top-K; writes selected idx + tanh(score)
// ---------------------------------------------------------------------------
__global__ void k_sort(const float* __restrict__ feat, const float* __restrict__ w) {
    __shared__ float sv[512];
    __shared__ int   si[512];
    __shared__ float s_inv;
    int tid = threadIdx.x, b = blockIdx.x;
    int warp = tid >> 5, lane = tid & 31;

    if (tid == 0) {
        float s = 0.f;
        #pragma unroll
        for (int i = 0; i < Ff; i++) s += w[i] * w[i];
        s_inv = rsqrtf(s);
    }
    const float* xg = feat + (size_t)11 * Nn * Ff + (size_t)b * NPG * Ff;
    float wl0 = w[lane], wl1 = w[lane + 32];
    for (int nd = warp; nd < NPG; nd += 16) {
        const float* x = xg + (size_t)nd * Ff;
        float v = x[lane] * wl0 + x[lane + 32] * wl1;
        #pragma unroll
        for (int o = 16; o > 0; o >>= 1) v += __shfl_down_sync(0xffffffffu, v, o);
        if (lane == 0) sv[nd] = v;
    }
    if (tid >= NPG) sv[tid] = __int_as_float(0xff800000);
    si[tid] = tid;
    __syncthreads();

    // Bitonic sort: value descending, index ascending on ties
    for (int k = 2; k <= 512; k <<= 1) {
        for (int j = k >> 1; j > 0; j >>= 1) {
            int ixj = tid ^ j;
            if (ixj > tid) {
                float va = sv[tid], vb = sv[ixj];
                int   ia = si[tid], ib = si[ixj];
                bool aFirst = (va > vb) || (va == vb && ia < ib);
                bool bFirst = (vb > va) || (vb == va && ib < ia);
                bool desc = ((tid & k) == 0);
                bool sw = desc ? bFirst : aFirst;
                if (sw) { sv[tid] = vb; sv[ixj] = va; si[tid] = ib; si[ixj] = ia; }
            }
            __syncthreads();
        }
    }
    if (tid < Kk) {
        g_selidx[b * Kk + tid] = si[tid];
        g_stanh[b * Kk + tid]  = tanhf(sv[tid] * s_inv);
    }
}

// ---------------------------------------------------------------------------
// Kernel: gather + BatchNorm -> bf16 xn   grid (64, 8)
// ---------------------------------------------------------------------------
__global__ void k_bn(const float* __restrict__ feat,
                     const float* __restrict__ bn_mean, const float* __restrict__ bn_var,
                     const float* __restrict__ bn_gamma, const float* __restrict__ bn_beta) {
    int b = blockIdx.x, q = blockIdx.y, tid = threadIdx.x;
    const float* xg = feat + (size_t)11 * Nn * Ff + (size_t)b * NPG * Ff;
    int base = q * (LIN / 8);
    for (int t = tid; t < LIN / 8; t += 256) {
        int i = base + t;
        int r = i >> 6, f = i & 63;
        int idx = g_selidx[b * Kk + r];
        float st = g_stanh[b * Kk + r];
        float xv = xg[idx * Ff + f];
        float xn = (xv * st - bn_mean[i]) * rsqrtf(bn_var[i] + BN_EPS) * bn_gamma[i] + bn_beta[i];
        g_xb[(size_t)b * LIN + i] = __float2bfloat16(xn);
    }
}

// ---------------------------------------------------------------------------
// GEMM1:  hpart[s][m][j] = sum_{k in chunk s} xn[m,k] * W1[j,k]
// bf16 mma.sync m16n8k16, W fp32->bf16 in-register, ldmatrix fragments.
// Block 256 thr (8 warps), warp tile 32m x 32j, BK=32, 2-stage smem.
// 3 CTAs/SM. grid (63, 7) = 441 CTAs = one wave.  (R8-proven structure)
// ---------------------------------------------------------------------------
#define BN1   128
#define BK1   32
#define ROWB  80                    // bytes per smem row (40 halves)
#define W_BYTES (128 * ROWB)        // 10240
#define X_BYTES (64 * ROWB)         // 5120
#define STG_B   (W_BYTES + X_BYTES) // 15360

__device__ __forceinline__ void mma16816(float* d,
                                         unsigned a0, unsigned a1, unsigned a2, unsigned a3,
                                         unsigned b0, unsigned b1) {
    asm volatile(
        "mma.sync.aligned.m16n8k16.row.col.f32.bf16.bf16.f32 "
        "{%0,%1,%2,%3}, {%4,%5,%6,%7}, {%8,%9}, {%0,%1,%2,%3};\n"
        : "+f"(d[0]), "+f"(d[1]), "+f"(d[2]), "+f"(d[3])
        : "r"(a0), "r"(a1), "r"(a2), "r"(a3), "r"(b0), "r"(b1));
}

__device__ __forceinline__ void ldsm4(unsigned& r0, unsigned& r1, unsigned& r2, unsigned& r3,
                                      unsigned addr) {
    asm volatile("ldmatrix.sync.aligned.m8n8.x4.shared.b16 {%0,%1,%2,%3}, [%4];"
                 : "=r"(r0), "=r"(r1), "=r"(r2), "=r"(r3) : "r"(addr));
}

__global__ __launch_bounds__(256, 3) void k_gemm1(const float* __restrict__ W1) {
    __shared__ __align__(16) unsigned char sm[2 * STG_B];
    unsigned smbase = (unsigned)__cvta_generic_to_shared(sm);

    int tid  = threadIdx.x;
    int warp = tid >> 5, lane = tid & 31;
    int wm = warp >> 2, wj = warp & 3;
    int gi = lane >> 2, qi = lane & 3;
    int jbase = blockIdx.x * BN1;
    int kbase = blockIdx.y * KCH;
    int iters = (blockIdx.y == KSPLIT - 1) ? 68 : 72;   // 68*32=2176, 72*32=2304

    // W load mapping: 4 float4/thread. chunk c = tid + i*256: row=c>>3, c8=c&7
    const float* wsrc[4]; unsigned wdst[4];
    #pragma unroll
    for (int i = 0; i < 4; i++) {
        int c = tid + i * 256;
        int row = c >> 3, c8 = c & 7;
        int j = jbase + row; if (j > Hh - 1) j = Hh - 1;
        wsrc[i] = W1 + (size_t)j * LIN + kbase + c8 * 4;
        wdst[i] = smbase + row * ROWB + c8 * 8;
    }
    // X load mapping: all 256 threads, 1 uint4 (8 halves). row=tid>>2, seg=tid&3
    const __nv_bfloat16* xsrc; unsigned xdst;
    {
        int row = tid >> 2, seg = tid & 3;
        xsrc = g_xb + (size_t)row * LIN + kbase + seg * 8;
        xdst = smbase + W_BYTES + row * ROWB + seg * 16;
    }

    // ldmatrix per-lane offsets (row stride 80B; conflict-free)
    unsigned offA = (unsigned)((lane & 15) * ROWB + (lane >> 4) * 16);
    unsigned offB = (unsigned)((((lane >> 4) & 1) * 8 + (lane & 7)) * ROWB + ((lane >> 3) & 1) * 16);
    unsigned aAddr0 = smbase + W_BYTES + (wm * 32) * ROWB + offA;       // mt=0
    unsigned aAddr1 = aAddr0 + 16 * ROWB;                                // mt=1
    unsigned bAddr0 = smbase + (wj * 32) * ROWB + offB;                  // nt pair 0
    unsigned bAddr1 = bAddr0 + 16 * ROWB;                                // nt pair 1

    float acc[2][4][4];
    #pragma unroll
    for (int a = 0; a < 2; a++)
        #pragma unroll
        for (int b = 0; b < 4; b++)
            #pragma unroll
            for (int q = 0; q < 4; q++) acc[a][b][q] = 0.f;

    // prologue: iter-0 data into registers
    float4 wv[4];
    #pragma unroll
    for (int i = 0; i < 4; i++) wv[i] = *(const float4*)(wsrc[i]);
    uint4 x0 = *(const uint4*)(xsrc);

    #pragma unroll 2
    for (int it = 0; it < iters; it++) {
        unsigned st = (unsigned)(it & 1) * STG_B;

        // STS: convert W to bf16 (8B each), copy X (16B)
        #pragma unroll
        for (int i = 0; i < 4; i++) {
            __nv_bfloat162 p0 = __floats2bfloat162_rn(wv[i].x, wv[i].y);
            __nv_bfloat162 p1 = __floats2bfloat162_rn(wv[i].z, wv[i].w);
            asm volatile("st.shared.v2.b32 [%0], {%1,%2};"
                         :: "r"(wdst[i] + st), "r"(*(unsigned*)&p0), "r"(*(unsigned*)&p1));
        }
        asm volatile("st.shared.v4.b32 [%0], {%1,%2,%3,%4};"
                     :: "r"(xdst + st), "r"(x0.x), "r"(x0.y), "r"(x0.z), "r"(x0.w));
        __syncthreads();

        // prefetch next iteration (hidden under this iteration's MMAs)
        if (it + 1 < iters) {
            int ko = (it + 1) * BK1;
            #pragma unroll
            for (int i = 0; i < 4; i++) wv[i] = *(const float4*)(wsrc[i] + ko);
            x0 = *(const uint4*)(xsrc + ko);
        }

        // two k16 sub-chunks
        #pragma unroll
        for (int kk = 0; kk < 2; kk++) {
            unsigned ko = (unsigned)(kk * 32);   // 16 halves = 32B
            unsigned a0[2], a1[2], a2[2], a3[2];
            ldsm4(a0[0], a1[0], a2[0], a3[0], aAddr0 + st + ko);
            ldsm4(a0[1], a1[1], a2[1], a3[1], aAddr1 + st + ko);
            unsigned b00, b01, b10, b11;
            ldsm4(b00, b01, b10, b11, bAddr0 + st + ko);
            #pragma unroll
            for (int mt = 0; mt < 2; mt++) {
                mma16816(acc[mt][0], a0[mt], a1[mt], a2[mt], a3[mt], b00, b01);
                mma16816(acc[mt][1], a0[mt], a1[mt], a2[mt], a3[mt], b10, b11);
            }
            ldsm4(b00, b01, b10, b11, bAddr1 + st + ko);
            #pragma unroll
            for (int mt = 0; mt < 2; mt++) {
                mma16816(acc[mt][2], a0[mt], a1[mt], a2[mt], a3[mt], b00, b01);
                mma16816(acc[mt][3], a0[mt], a1[mt], a2[mt], a3[mt], b10, b11);
            }
        }
        __syncthreads();
    }

    // epilogue: plain STG into split-private partials
    float* hp = &g_hpart[blockIdx.y][0][0];
    #pragma unroll
    for (int mt = 0; mt < 2; mt++) {
        #pragma unroll
        for (int nt = 0; nt < 4; nt++) {
            int m = wm * 32 + mt * 16 + gi;
            int j = jbase + wj * 32 + nt * 8 + qi * 2;
            if (j < Hh) {
                *(float2*)(hp + (size_t)m * Hh + j) =
                    make_float2(acc[mt][nt][0], acc[mt][nt][1]);
                *(float2*)(hp + (size_t)(m + 8) * Hh + j) =
                    make_float2(acc[mt][nt][2], acc[mt][nt][3]);
            }
        }
    }
}

// ---------------------------------------------------------------------------
// GEMM2 + split-reduce + bias + relu + (last block) loss.  grid (64,16), 256 thr.
// ---------------------------------------------------------------------------
__global__ void k_gemm2(const float* __restrict__ b1, const float* __restrict__ W2,
                        const float* __restrict__ b2, float* __restrict__ out) {
    int m = blockIdx.x, q = blockIdx.y, tid = threadIdx.x;
    int jq = q * (Hh / G2SPLIT);          // 500 per split
    float s = 0.f;
    for (int t = tid * 4; t < Hh / G2SPLIT; t += 1024) {
        int j = jq + t;
        float4 hs = make_float4(0.f, 0.f, 0.f, 0.f);
        #pragma unroll
        for (int sp = 0; sp < KSPLIT; sp++) {
            float4 hv = *(const float4*)(&g_hpart[sp][m][j]);
            hs.x += hv.x; hs.y += hv.y; hs.z += hv.z; hs.w += hv.w;
        }
        float4 bv = *(const float4*)(b1 + j);
        float4 wv = *(const float4*)(W2 + j);
        s += fmaxf(hs.x + bv.x, 0.f) * wv.x;
        s += fmaxf(hs.y + bv.y, 0.f) * wv.y;
        s += fmaxf(hs.z + bv.z, 0.f) * wv.z;
        s += fmaxf(hs.w + bv.w, 0.f) * wv.w;
    }
    #pragma unroll
    for (int o = 16; o > 0; o >>= 1) s += __shfl_down_sync(0xffffffffu, s, o);
    __shared__ float red[8];
    if ((tid & 31) == 0) red[tid >> 5] = s;
    __syncthreads();
    if (tid == 0) {
        float t8 = 0.f;
        #pragma unroll
        for (int i = 0; i < 8; i++) t8 += red[i];
        g_l2[m * G2SPLIT + q] = t8;
    }

    // last-block loss: writers fence before count; count-full implies all
    // g_l2 stores visible to the last block.
    __shared__ int is_last;
    __threadfence();
    if (tid == 0) {
        int old = atomicAdd(&g_done, 1);
        is_last = (old == Bb * G2SPLIT - 1) ? 1 : 0;
    }
    __syncthreads();
    if (is_last) {
        float per = 0.f;
        if (tid < Bb) {
            float l = b2[0];
            #pragma unroll
            for (int qq = 0; qq < G2SPLIT; qq++) l += g_l2[tid * G2SPLIT + qq];
            per = (l > 0.f) ? log1pf(expf(-l)) : (log1pf(expf(l)) - l);
        }
        #pragma unroll
        for (int o = 16; o > 0; o >>= 1) per += __shfl_down_sync(0xffffffffu, per, o);
        __shared__ float r2[2];
        if (tid < Bb && (tid & 31) == 0) r2[tid >> 5] = per;
        __syncthreads();
        if (tid == 0) {
            out[0] = (r2[0] + r2[1]) * (1.0f / Bb);
            g_done = 0;   // reset for next graph replay (deterministic)
        }
    }
}

// ---------------------------------------------------------------------------
extern "C" void kernel_launch(void* const* d_in, const int* in_sizes, int n_in,
                              void* d_out, int out_size) {
    const float* feat     = (const float*)d_in[0];
    const float* w        = (const float*)d_in[3];
    const float* bn_gamma = (const float*)d_in[4];
    const float* bn_beta  = (const float*)d_in[5];
    const float* bn_mean  = (const float*)d_in[6];
    const float* bn_var   = (const float*)d_in[7];
    const float* W1       = (const float*)d_in[8];
    const float* b1       = (const float*)d_in[9];
    const float* W2       = (const float*)d_in[10];
    const float* b2       = (const float*)d_in[11];

    k_sort<<<Bb, 512>>>(feat, w);
    dim3 gbn(Bb, 8);
    k_bn<<<gbn, 256>>>(feat, bn_mean, bn_var, bn_gamma, bn_beta);
    dim3 g1(63, KSPLIT);   // 441 CTAs, 3/SM -> one wave
    k_gemm1<<<g1, 256>>>(W1);
    dim3 g2(Bb, G2SPLIT);
    k_gemm2<<<g2, 256>>>(b1, W2, b2, (float*)d_out);
}

// round 12
// speedup vs baseline: 1.2278x; 1.1811x over previous
#include <cuda_runtime.h>
#include <cuda_bf16.h>
#include <math.h>
#include <stdint.h>

// Problem constants
#define Bb   64
#define NPG  400
#define Kk   250
#define Ff   64
#define LIN  16000
#define Hh   8000
#define Nn   (Bb*NPG)        // 25600
#define BN_EPS 1e-5f

#define KSPLIT 8             // 7 chunks of 2048 + 1 of 1664
#define G2SPLIT 2

// Scratch (device globals; no allocation allowed)
__device__ __nv_bfloat16 g_xb[Bb*LIN];      // bf16 normalized features
__device__ int   g_selidx[Bb*Kk];
__device__ float g_stanh[Bb*Kk];
__device__ float g_hpart[KSPLIT][Bb][Hh];   // split-K partials
__device__ float g_l2[Bb*G2SPLIT];          // gemm2 partial logits
__device__ int   g_done;                    // gemm2 completion counter (zero-init)

// ---------------------------------------------------------------------------
// Kernel: fused scores + bitonic top-K; writes selected idx + tanh(score)
// ---------------------------------------------------------------------------
__global__ void k_sort(const float* __restrict__ feat, const float* __restrict__ w) {
    __shared__ float sv[512];
    __shared__ int   si[512];
    __shared__ float s_inv;
    int tid = threadIdx.x, b = blockIdx.x;
    int warp = tid >> 5, lane = tid & 31;

    if (tid == 0) {
        float s = 0.f;
        #pragma unroll
        for (int i = 0; i < Ff; i++) s += w[i] * w[i];
        s_inv = rsqrtf(s);
    }
    const float* xg = feat + (size_t)11 * Nn * Ff + (size_t)b * NPG * Ff;
    float wl0 = w[lane], wl1 = w[lane + 32];
    for (int nd = warp; nd < NPG; nd += 16) {
        const float* x = xg + (size_t)nd * Ff;
        float v = x[lane] * wl0 + x[lane + 32] * wl1;
        #pragma unroll
        for (int o = 16; o > 0; o >>= 1) v += __shfl_down_sync(0xffffffffu, v, o);
        if (lane == 0) sv[nd] = v;
    }
    if (tid >= NPG) sv[tid] = __int_as_float(0xff800000);
    si[tid] = tid;
    __syncthreads();

    // Bitonic sort: value descending, index ascending on ties
    for (int k = 2; k <= 512; k <<= 1) {
        for (int j = k >> 1; j > 0; j >>= 1) {
            int ixj = tid ^ j;
            if (ixj > tid) {
                float va = sv[tid], vb = sv[ixj];
                int   ia = si[tid], ib = si[ixj];
                bool aFirst = (va > vb) || (va == vb && ia < ib);
                bool bFirst = (vb > va) || (vb == va && ib < ia);
                bool desc = ((tid & k) == 0);
                bool sw = desc ? bFirst : aFirst;
                if (sw) { sv[tid] = vb; sv[ixj] = va; si[tid] = ib; si[ixj] = ia; }
            }
            __syncthreads();
        }
    }
    if (tid < Kk) {
        g_selidx[b * Kk + tid] = si[tid];
        g_stanh[b * Kk + tid]  = tanhf(sv[tid] * s_inv);
    }
}

// ---------------------------------------------------------------------------
// Kernel: gather + BatchNorm -> bf16 xn   grid (64, 8)
// ---------------------------------------------------------------------------
__global__ void k_bn(const float* __restrict__ feat,
                     const float* __restrict__ bn_mean, const float* __restrict__ bn_var,
                     const float* __restrict__ bn_gamma, const float* __restrict__ bn_beta) {
    int b = blockIdx.x, q = blockIdx.y, tid = threadIdx.x;
    const float* xg = feat + (size_t)11 * Nn * Ff + (size_t)b * NPG * Ff;
    int base = q * (LIN / 8);
    for (int t = tid; t < LIN / 8; t += 256) {
        int i = base + t;
        int r = i >> 6, f = i & 63;
        int idx = g_selidx[b * Kk + r];
        float st = g_stanh[b * Kk + r];
        float xv = xg[idx * Ff + f];
        float xn = (xv * st - bn_mean[i]) * rsqrtf(bn_var[i] + BN_EPS) * bn_gamma[i] + bn_beta[i];
        g_xb[(size_t)b * LIN + i] = __float2bfloat16(xn);
    }
}

// ---------------------------------------------------------------------------
// GEMM1:  hpart[s][m][j] = sum_{k in chunk s} xn[m,k] * W1[j,k]
// 128 thr (4 warps), warp tile 32m x 64j, BN=128, BK=32, 2-stage smem,
// 4 CTAs/SM. W: LDG fp32 -> bf16 regs -> STS. X: cp.async.
// grid (63, 8) = 504 CTAs, one wave. Last j-block overlaps (benign dup writes).
// ---------------------------------------------------------------------------
#define BN1   128
#define BK1   32
#define ROWB  80                    // bytes per smem row (40 halves)
#define W_BYTES (128 * ROWB)        // 10240
#define X_BYTES (64 * ROWB)         // 5120
#define STG_B   (W_BYTES + X_BYTES) // 15360

__device__ __forceinline__ void mma16816(float* d,
                                         unsigned a0, unsigned a1, unsigned a2, unsigned a3,
                                         unsigned b0, unsigned b1) {
    asm volatile(
        "mma.sync.aligned.m16n8k16.row.col.f32.bf16.bf16.f32 "
        "{%0,%1,%2,%3}, {%4,%5,%6,%7}, {%8,%9}, {%0,%1,%2,%3};\n"
        : "+f"(d[0]), "+f"(d[1]), "+f"(d[2]), "+f"(d[3])
        : "r"(a0), "r"(a1), "r"(a2), "r"(a3), "r"(b0), "r"(b1));
}

__device__ __forceinline__ void ldsm4(unsigned& r0, unsigned& r1, unsigned& r2, unsigned& r3,
                                      unsigned addr) {
    asm volatile("ldmatrix.sync.aligned.m8n8.x4.shared.b16 {%0,%1,%2,%3}, [%4];"
                 : "=r"(r0), "=r"(r1), "=r"(r2), "=r"(r3) : "r"(addr));
}

__device__ __forceinline__ void cpa16(unsigned dst, const void* src) {
    asm volatile("cp.async.cg.shared.global [%0], [%1], 16;" :: "r"(dst), "l"(src));
}

__global__ __launch_bounds__(128, 4) void k_gemm1(const float* __restrict__ W1) {
    __shared__ __align__(16) unsigned char sm[2 * STG_B];
    unsigned smbase = (unsigned)__cvta_generic_to_shared(sm);

    int tid  = threadIdx.x;
    int warp = tid >> 5, lane = tid & 31;
    int wm = warp >> 1, wj = warp & 1;          // 2x2 warp grid
    int gi = lane >> 2, qi = lane & 3;
    int jbase = blockIdx.x * BN1;
    if (jbase > Hh - BN1) jbase = Hh - BN1;     // overlap last block (dup writes benign)
    int kbase = blockIdx.y * 2048;
    int iters = (blockIdx.y == KSPLIT - 1) ? 52 : 64;  // 52*32=1664, 64*32=2048

    // W mapping: 8 float4/thread. chunk c = tid + i*128: row = (tid>>3)+i*16, c8 = tid&7
    int wrow0 = tid >> 3, wc8 = tid & 7;
    const float* wbase = W1 + (size_t)(jbase + wrow0) * LIN + kbase + wc8 * 4;
    unsigned wdst0 = smbase + (unsigned)(wrow0 * ROWB + wc8 * 8);

    // X mapping (cp.async): 2 chunks/thread. row = (tid>>2)+i*32, seg = tid&3
    int xrow0 = tid >> 2, xseg = tid & 3;
    const __nv_bfloat16* xbase = g_xb + (size_t)xrow0 * LIN + kbase + xseg * 8;
    unsigned xdst0 = smbase + (unsigned)(W_BYTES + xrow0 * ROWB + xseg * 16);

    // ldmatrix per-lane offsets (row stride 80B; conflict-free)
    unsigned offA = (unsigned)((lane & 15) * ROWB + (lane >> 4) * 16);
    unsigned offB = (unsigned)((((lane >> 4) & 1) * 8 + (lane & 7)) * ROWB + ((lane >> 3) & 1) * 16);
    unsigned aAddr0 = smbase + W_BYTES + (wm * 32) * ROWB + offA;       // mt=0
    unsigned aAddr1 = aAddr0 + 16 * ROWB;                                // mt=1
    unsigned bAddrB = smbase + (wj * 64) * ROWB + offB;                  // nt pairs at +p*16*ROWB

    float acc[2][8][4];
    #pragma unroll
    for (int a = 0; a < 2; a++)
        #pragma unroll
        for (int b = 0; b < 8; b++)
            #pragma unroll
            for (int q = 0; q < 4; q++) acc[a][b][q] = 0.f;

    // prologue: X stage 0 via cp.async; W iter 0 into registers
    #pragma unroll
    for (int i = 0; i < 2; i++)
        cpa16(xdst0 + i * (32 * ROWB), xbase + (size_t)i * 32 * LIN);
    asm volatile("cp.async.commit_group;");
    float4 wv[8];
    #pragma unroll
    for (int i = 0; i < 8; i++)
        wv[i] = *(const float4*)(wbase + (size_t)i * 16 * LIN);

    #pragma unroll 2
    for (int it = 0; it < iters; it++) {
        unsigned st = (unsigned)(it & 1) * STG_B;
        unsigned sn = (unsigned)((it + 1) & 1) * STG_B;

        // STS: convert W to bf16 (8B per chunk)
        #pragma unroll
        for (int i = 0; i < 8; i++) {
            __nv_bfloat162 p0 = __floats2bfloat162_rn(wv[i].x, wv[i].y);
            __nv_bfloat162 p1 = __floats2bfloat162_rn(wv[i].z, wv[i].w);
            asm volatile("st.shared.v2.b32 [%0], {%1,%2};"
                         :: "r"(wdst0 + st + (unsigned)(i * 16 * ROWB)),
                            "r"(*(unsigned*)&p0), "r"(*(unsigned*)&p1));
        }

        // issue next-iter loads (X cp.async into other stage; W LDG into regs)
        if (it + 1 < iters) {
            int ko = (it + 1) * BK1;
            #pragma unroll
            for (int i = 0; i < 2; i++)
                cpa16(xdst0 + sn + i * (32 * ROWB), xbase + (size_t)i * 32 * LIN + ko);
            #pragma unroll
            for (int i = 0; i < 8; i++)
                wv[i] = *(const float4*)(wbase + (size_t)i * 16 * LIN + ko);
        }
        asm volatile("cp.async.commit_group;");
        asm volatile("cp.async.wait_group 1;");   // current iter's X group done
        __syncthreads();

        // two k16 sub-chunks: per warp 6 LDSM + 16 MMA each
        #pragma unroll
        for (int kk = 0; kk < 2; kk++) {
            unsigned ko = st + (unsigned)(kk * 32);   // 16 halves = 32B
            unsigned a0[2], a1[2], a2[2], a3[2];
            ldsm4(a0[0], a1[0], a2[0], a3[0], aAddr0 + ko);
            ldsm4(a0[1], a1[1], a2[1], a3[1], aAddr1 + ko);
            #pragma unroll
            for (int p = 0; p < 4; p++) {            // n-tile pairs
                unsigned b00, b01, b10, b11;
                ldsm4(b00, b01, b10, b11, bAddrB + ko + (unsigned)(p * 16 * ROWB));
                #pragma unroll
                for (int mt = 0; mt < 2; mt++) {
                    mma16816(acc[mt][p * 2],     a0[mt], a1[mt], a2[mt], a3[mt], b00, b01);
                    mma16816(acc[mt][p * 2 + 1], a0[mt], a1[mt], a2[mt], a3[mt], b10, b11);
                }
            }
        }
        __syncthreads();
    }

    // epilogue: plain STG into split-private partials (no guard; overlap benign)
    float* hp = &g_hpart[blockIdx.y][0][0];
    #pragma unroll
    for (int mt = 0; mt < 2; mt++) {
        #pragma unroll
        for (int nt = 0; nt < 8; nt++) {
            int m = wm * 32 + mt * 16 + gi;
            int j = jbase + wj * 64 + nt * 8 + qi * 2;
            *(float2*)(hp + (size_t)m * Hh + j) =
                make_float2(acc[mt][nt][0], acc[mt][nt][1]);
            *(float2*)(hp + (size_t)(m + 8) * Hh + j) =
                make_float2(acc[mt][nt][2], acc[mt][nt][3]);
        }
    }
}

// ---------------------------------------------------------------------------
// GEMM2 + split-reduce + bias + relu + (last block) loss. grid (64,2), 512 thr.
// ---------------------------------------------------------------------------
__global__ void k_gemm2(const float* __restrict__ b1, const float* __restrict__ W2,
                        const float* __restrict__ b2, float* __restrict__ out) {
    int m = blockIdx.x, q = blockIdx.y, tid = threadIdx.x;
    int jq = q * (Hh / G2SPLIT);          // 4000 per split
    float s = 0.f;
    #pragma unroll
    for (int i = 0; i < 2; i++) {
        int t = tid + i * 512;
        if (t < (Hh / G2SPLIT) / 4) {
            int j = jq + t * 4;
            float4 hs = make_float4(0.f, 0.f, 0.f, 0.f);
            #pragma unroll
            for (int sp = 0; sp < KSPLIT; sp++) {
                float4 hv = *(const float4*)(&g_hpart[sp][m][j]);
                hs.x += hv.x; hs.y += hv.y; hs.z += hv.z; hs.w += hv.w;
            }
            float4 bv = *(const float4*)(b1 + j);
            float4 wv = *(const float4*)(W2 + j);
            s += fmaxf(hs.x + bv.x, 0.f) * wv.x;
            s += fmaxf(hs.y + bv.y, 0.f) * wv.y;
            s += fmaxf(hs.z + bv.z, 0.f) * wv.z;
            s += fmaxf(hs.w + bv.w, 0.f) * wv.w;
        }
    }
    #pragma unroll
    for (int o = 16; o > 0; o >>= 1) s += __shfl_down_sync(0xffffffffu, s, o);
    __shared__ float red[16];
    if ((tid & 31) == 0) red[tid >> 5] = s;
    __syncthreads();
    if (tid == 0) {
        float t16 = 0.f;
        #pragma unroll
        for (int i = 0; i < 16; i++) t16 += red[i];
        g_l2[m * G2SPLIT + q] = t16;
    }

    // last-block loss
    __shared__ int is_last;
    __threadfence();
    if (tid == 0) {
        int old = atomicAdd(&g_done, 1);
        is_last = (old == Bb * G2SPLIT - 1) ? 1 : 0;
    }
    __syncthreads();
    if (is_last) {
        float per = 0.f;
        if (tid < Bb) {
            float l = b2[0];
            #pragma unroll
            for (int qq = 0; qq < G2SPLIT; qq++) l += g_l2[tid * G2SPLIT + qq];
            per = (l > 0.f) ? log1pf(expf(-l)) : (log1pf(expf(l)) - l);
        }
        #pragma unroll
        for (int o = 16; o > 0; o >>= 1) per += __shfl_down_sync(0xffffffffu, per, o);
        __shared__ float r2[2];
        if (tid < Bb && (tid & 31) == 0) r2[tid >> 5] = per;
        __syncthreads();
        if (tid == 0) {
            out[0] = (r2[0] + r2[1]) * (1.0f / Bb);
            g_done = 0;   // reset for graph replay determinism
        }
    }
}

// ---------------------------------------------------------------------------
extern "C" void kernel_launch(void* const* d_in, const int* in_sizes, int n_in,
                              void* d_out, int out_size) {
    const float* feat     = (const float*)d_in[0];
    const float* w        = (const float*)d_in[3];
    const float* bn_gamma = (const float*)d_in[4];
    const float* bn_beta  = (const float*)d_in[5];
    const float* bn_mean  = (const float*)d_in[6];
    const float* bn_var   = (const float*)d_in[7];
    const float* W1       = (const float*)d_in[8];
    const float* b1       = (const float*)d_in[9];
    const float* W2       = (const float*)d_in[10];
    const float* b2       = (const float*)d_in[11];

    k_sort<<<Bb, 512>>>(feat, w);
    dim3 gbn(Bb, 8);
    k_bn<<<gbn, 256>>>(feat, bn_mean, bn_var, bn_gamma, bn_beta);
    dim3 g1(63, KSPLIT);   // 504 CTAs, 4/SM -> one wave
    k_gemm1<<<g1, 128>>>(W1);
    dim3 g2(Bb, G2SPLIT);
    k_gemm2<<<g2, 512>>>(b1, W2, b2, (float*)d_out);
}